// round 1
// baseline (speedup 1.0000x reference)
#include <cuda_runtime.h>
#include <math.h>

#define B_  8
#define S_  4096
#define H_  768
#define D_  64
#define TM  64      // rows per block tile
#define TK  32      // K-chunk for projection GEMM
#define BT  64      // attention seq tile

// Scratch for projected q,k,v: [B,S,D] each = 2M floats = 8MB
__device__ float g_q[B_ * S_ * D_];
__device__ float g_k[B_ * S_ * D_];
__device__ float g_v[B_ * S_ * D_];

// ---------------------------------------------------------------------------
// Kernel 1: fused QKV projection.  out[p] = x @ W[p] + b[p]
// grid = (S_*B_/TM, 3), block = 256 threads (16x16), 4x4 microtile per thread.
// ---------------------------------------------------------------------------
__global__ void __launch_bounds__(256) qkv_kernel(
    const float* __restrict__ x,
    const float* __restrict__ Wq, const float* __restrict__ bq,
    const float* __restrict__ Wk, const float* __restrict__ bk,
    const float* __restrict__ Wv, const float* __restrict__ bv)
{
    const float* W;
    const float* bias;
    float* out;
    int p = blockIdx.y;
    if (p == 0)      { W = Wq; bias = bq; out = g_q; }
    else if (p == 1) { W = Wk; bias = bk; out = g_k; }
    else             { W = Wv; bias = bv; out = g_v; }

    __shared__ float xs[TM][TK + 1];   // +1 pad to break bank conflicts
    __shared__ float ws[TK][D_];

    const int tid = threadIdx.x;
    const int tx = tid & 15;
    const int ty = tid >> 4;
    const int row0 = blockIdx.x * TM;

    float acc[4][4] = {};

    for (int k0 = 0; k0 < H_; k0 += TK) {
        // load x tile 64x32 (coalesced: 32 consecutive floats per row)
        #pragma unroll
        for (int i = 0; i < 8; i++) {
            int e = tid + i * 256;
            int r = e >> 5, c = e & 31;
            xs[r][c] = x[(size_t)(row0 + r) * H_ + k0 + c];
        }
        // load W tile 32x64 (coalesced)
        #pragma unroll
        for (int i = 0; i < 8; i++) {
            int e = tid + i * 256;
            int r = e >> 6, c = e & 63;
            ws[r][c] = W[(size_t)(k0 + r) * D_ + c];
        }
        __syncthreads();

        #pragma unroll
        for (int kk = 0; kk < TK; kk++) {
            float a[4], bb[4];
            #pragma unroll
            for (int i = 0; i < 4; i++) a[i]  = xs[ty * 4 + i][kk];
            #pragma unroll
            for (int j = 0; j < 4; j++) bb[j] = ws[kk][tx * 4 + j];
            #pragma unroll
            for (int i = 0; i < 4; i++)
                #pragma unroll
                for (int j = 0; j < 4; j++)
                    acc[i][j] = fmaf(a[i], bb[j], acc[i][j]);
        }
        __syncthreads();
    }

    #pragma unroll
    for (int i = 0; i < 4; i++) {
        int r = row0 + ty * 4 + i;
        #pragma unroll
        for (int j = 0; j < 4; j++) {
            int c = tx * 4 + j;
            out[(size_t)r * D_ + c] = acc[i][j] + bias[c];
        }
    }
}

// ---------------------------------------------------------------------------
// Kernel 2: causal flash attention over g_q/g_k/g_v, writes final out.
// grid = (S_/BT, B_), block = 256 threads (16x16).
// Each block: one 64-row query tile, loops k-tiles 0..qt with online softmax.
// Dynamic smem: Q,K,V,P tiles of 64x65 floats = 66560 bytes.
// ---------------------------------------------------------------------------
#define SM_STRIDE 65
#define ATTN_SMEM (4 * BT * SM_STRIDE * (int)sizeof(float))

__global__ void __launch_bounds__(256) attn_kernel(float* __restrict__ out)
{
    extern __shared__ float sm[];
    float* Qs = sm;
    float* Ks = Qs + BT * SM_STRIDE;
    float* Vs = Ks + BT * SM_STRIDE;
    float* Ps = Vs + BT * SM_STRIDE;

    const int b  = blockIdx.y;
    const int qt = gridDim.x - 1 - blockIdx.x;   // heaviest tiles first
    const int tid = threadIdx.x;
    const int tx = tid & 15;
    const int ty = tid >> 4;

    const float* q = g_q + (size_t)b * S_ * D_;
    const float* k = g_k + (size_t)b * S_ * D_;
    const float* v = g_v + (size_t)b * S_ * D_;

    // load Q tile (64x64, coalesced)
    #pragma unroll
    for (int i = 0; i < 16; i++) {
        int e = tid + i * 256;
        int r = e >> 6, c = e & 63;
        Qs[r * SM_STRIDE + c] = q[(size_t)(qt * BT + r) * D_ + c];
    }

    float m[4], l[4], o[4][4];
    #pragma unroll
    for (int i = 0; i < 4; i++) {
        m[i] = -1e30f; l[i] = 0.f;
        #pragma unroll
        for (int j = 0; j < 4; j++) o[i][j] = 0.f;
    }

    const float scale = 0.125f;   // 1/sqrt(64)

    for (int kt = 0; kt <= qt; kt++) {
        __syncthreads();   // previous PV reads of Ks/Vs done
        #pragma unroll
        for (int i = 0; i < 16; i++) {
            int e = tid + i * 256;
            int r = e >> 6, c = e & 63;
            Ks[r * SM_STRIDE + c] = k[(size_t)(kt * BT + r) * D_ + c];
            Vs[r * SM_STRIDE + c] = v[(size_t)(kt * BT + r) * D_ + c];
        }
        __syncthreads();

        // s[i][j] = sum_d Q[ty*4+i][d] * K[tx*4+j][d]
        float s[4][4] = {};
        #pragma unroll 16
        for (int d = 0; d < D_; d++) {
            float a[4], bb[4];
            #pragma unroll
            for (int i = 0; i < 4; i++) a[i]  = Qs[(ty * 4 + i) * SM_STRIDE + d];
            #pragma unroll
            for (int j = 0; j < 4; j++) bb[j] = Ks[(tx * 4 + j) * SM_STRIDE + d];
            #pragma unroll
            for (int i = 0; i < 4; i++)
                #pragma unroll
                for (int j = 0; j < 4; j++)
                    s[i][j] = fmaf(a[i], bb[j], s[i][j]);
        }

        const bool diag = (kt == qt);
        #pragma unroll
        for (int i = 0; i < 4; i++)
            #pragma unroll
            for (int j = 0; j < 4; j++) {
                s[i][j] *= scale;
                if (diag && (tx * 4 + j) > (ty * 4 + i)) s[i][j] = -1e30f;
            }

        // online softmax update per row
        #pragma unroll
        for (int i = 0; i < 4; i++) {
            float mt = fmaxf(fmaxf(s[i][0], s[i][1]), fmaxf(s[i][2], s[i][3]));
            #pragma unroll
            for (int off = 8; off >= 1; off >>= 1)
                mt = fmaxf(mt, __shfl_xor_sync(0xffffffffu, mt, off));
            float mnew = fmaxf(m[i], mt);
            float corr = __expf(m[i] - mnew);
            m[i] = mnew;

            float rs = 0.f;
            #pragma unroll
            for (int j = 0; j < 4; j++) {
                float pv = __expf(s[i][j] - mnew);
                Ps[(ty * 4 + i) * SM_STRIDE + tx * 4 + j] = pv;
                rs += pv;
            }
            #pragma unroll
            for (int off = 8; off >= 1; off >>= 1)
                rs += __shfl_xor_sync(0xffffffffu, rs, off);

            l[i] = l[i] * corr + rs;
            #pragma unroll
            for (int j = 0; j < 4; j++) o[i][j] *= corr;
        }
        __syncthreads();   // all of Ps written

        // O += P @ V : o[i][j] += sum_kk P[ty*4+i][kk] * V[kk][tx*4+j]
        #pragma unroll 8
        for (int kk = 0; kk < BT; kk++) {
            float pp[4], vv[4];
            #pragma unroll
            for (int i = 0; i < 4; i++) pp[i] = Ps[(ty * 4 + i) * SM_STRIDE + kk];
            #pragma unroll
            for (int j = 0; j < 4; j++) vv[j] = Vs[kk * SM_STRIDE + tx * 4 + j];
            #pragma unroll
            for (int i = 0; i < 4; i++)
                #pragma unroll
                for (int j = 0; j < 4; j++)
                    o[i][j] = fmaf(pp[i], vv[j], o[i][j]);
        }
    }

    #pragma unroll
    for (int i = 0; i < 4; i++) {
        float inv = 1.f / l[i];
        int r = qt * BT + ty * 4 + i;
        #pragma unroll
        for (int j = 0; j < 4; j++)
            out[((size_t)b * S_ + r) * D_ + tx * 4 + j] = o[i][j] * inv;
    }
}

// ---------------------------------------------------------------------------
extern "C" void kernel_launch(void* const* d_in, const int* in_sizes, int n_in,
                              void* d_out, int out_size)
{
    const float* x  = (const float*)d_in[0];
    const float* Wq = (const float*)d_in[1];
    const float* bq = (const float*)d_in[2];
    const float* Wk = (const float*)d_in[3];
    const float* bk = (const float*)d_in[4];
    const float* Wv = (const float*)d_in[5];
    const float* bv = (const float*)d_in[6];
    float* out = (float*)d_out;

    cudaFuncSetAttribute(attn_kernel,
                         cudaFuncAttributeMaxDynamicSharedMemorySize, ATTN_SMEM);

    dim3 g1((B_ * S_) / TM, 3);
    qkv_kernel<<<g1, 256>>>(x, Wq, bq, Wk, bk, Wv, bv);

    dim3 g2(S_ / BT, B_);
    attn_kernel<<<g2, 256, ATTN_SMEM>>>(out);
}

// round 3
// speedup vs baseline: 2.4321x; 2.4321x over previous
#include <cuda_runtime.h>

#define B_  8
#define S_  4096
#define H_  768
#define D_  64
#define BQ  128
#define BK  64
#define SSTR 68   // smem row stride in floats; 68 % 32 == 4 -> conflict-free frag loads

// scratch
__device__ float g_q [B_ * S_ * D_];        // [b*S + s][d]
__device__ float g_k [B_ * S_ * D_];        // [b*S + s][d]
__device__ float g_vt[B_ * D_ * S_];        // transposed: [b][d][s]
__device__ float g_wt[3][D_ * H_];          // W^T: [n][k] for q,k,v

__device__ __forceinline__ unsigned f2tf(float f) {
    unsigned u; asm("cvt.rna.tf32.f32 %0, %1;" : "=r"(u) : "f"(f)); return u;
}
__device__ __forceinline__ float tf(float f) { return __uint_as_float(f2tf(f)); }

__device__ __forceinline__ void mma8(float* c, unsigned a0, unsigned a1, unsigned a2, unsigned a3,
                                     unsigned b0, unsigned b1) {
    asm("mma.sync.aligned.m16n8k8.row.col.f32.tf32.tf32.f32 "
        "{%0,%1,%2,%3}, {%4,%5,%6,%7}, {%8,%9}, {%0,%1,%2,%3};"
        : "+f"(c[0]), "+f"(c[1]), "+f"(c[2]), "+f"(c[3])
        : "r"(a0), "r"(a1), "r"(a2), "r"(a3), "r"(b0), "r"(b1));
}

// ---------------------------------------------------------------------------
// Kernel 0: transpose W into g_wt (tiny; runs every call, deterministic)
// ---------------------------------------------------------------------------
__global__ void wt_kernel(const float* __restrict__ Wq,
                          const float* __restrict__ Wk,
                          const float* __restrict__ Wv) {
    int idx = blockIdx.x * blockDim.x + threadIdx.x;
    if (idx >= D_ * H_) return;
    int n = idx / H_, k = idx % H_;
    g_wt[0][idx] = Wq[k * D_ + n];
    g_wt[1][idx] = Wk[k * D_ + n];
    g_wt[2][idx] = Wv[k * D_ + n];
}

// ---------------------------------------------------------------------------
// Kernel 1: QKV projection with tf32 mma.  grid=(256,3), block=256 (8 warps).
// Block computes 128 rows x 64 cols.  Warp w: rows 16w..16w+15, all 64 cols.
// smem: xs[128][SSTR] + ws[64][SSTR] (W^T tile, [n][k])
// ---------------------------------------------------------------------------
#define QKV_SMEM ((BQ + 64) * SSTR * (int)sizeof(float))

__global__ void __launch_bounds__(256, 2) qkv_kernel(
    const float* __restrict__ x,
    const float* __restrict__ bq, const float* __restrict__ bk, const float* __restrict__ bv)
{
    extern __shared__ float sm[];
    float* xs = sm;                 // [128][SSTR]
    float* ws = sm + BQ * SSTR;     // [64][SSTR]  W^T tile: row n, col k_local

    const int p = blockIdx.y;
    const float* wt   = g_wt[p];
    const float* bias = (p == 0) ? bq : ((p == 1) ? bk : bv);

    const int tid = threadIdx.x;
    const int w = tid >> 5, lane = tid & 31, g = lane >> 2, t = lane & 3;
    const int row0 = blockIdx.x * BQ;

    float acc[8][4] = {};

    for (int k0 = 0; k0 < H_; k0 += 64) {
        __syncthreads();
        #pragma unroll
        for (int i = 0; i < 8; i++) {               // x tile 128x64
            int e = tid + i * 256;
            int r = e >> 4, c4 = (e & 15) * 4;
            float4 v = *(const float4*)&x[(size_t)(row0 + r) * H_ + k0 + c4];
            float* d = &xs[r * SSTR + c4];
            d[0] = tf(v.x); d[1] = tf(v.y); d[2] = tf(v.z); d[3] = tf(v.w);
        }
        #pragma unroll
        for (int i = 0; i < 4; i++) {               // W^T tile 64x64
            int e = tid + i * 256;
            int r = e >> 4, c4 = (e & 15) * 4;
            float4 v = *(const float4*)&wt[(size_t)r * H_ + k0 + c4];
            float* d = &ws[r * SSTR + c4];
            d[0] = tf(v.x); d[1] = tf(v.y); d[2] = tf(v.z); d[3] = tf(v.w);
        }
        __syncthreads();

        #pragma unroll
        for (int s = 0; s < 8; s++) {
            const float* ap = &xs[(16 * w + g) * SSTR + 8 * s + t];
            unsigned a0 = __float_as_uint(ap[0]);
            unsigned a1 = __float_as_uint(ap[8 * SSTR]);
            unsigned a2 = __float_as_uint(ap[4]);
            unsigned a3 = __float_as_uint(ap[8 * SSTR + 4]);
            #pragma unroll
            for (int j = 0; j < 8; j++) {
                // B[k][n] = W[k][n] = ws[n][k] ; b0=(k=8s+t, n=8j+g)
                unsigned b0 = __float_as_uint(ws[(8 * j + g) * SSTR + 8 * s + t]);
                unsigned b1 = __float_as_uint(ws[(8 * j + g) * SSTR + 8 * s + t + 4]);
                mma8(acc[j], a0, a1, a2, a3, b0, b1);
            }
        }
    }

    const int r_g = row0 + 16 * w + g;
    if (p < 2) {
        float* out = (p == 0) ? g_q : g_k;
        #pragma unroll
        for (int j = 0; j < 8; j++) {
            int c = 8 * j + 2 * t;
            float b0v = __ldg(&bias[c]), b1v = __ldg(&bias[c + 1]);
            *(float2*)&out[(size_t)r_g * D_ + c]       = make_float2(acc[j][0] + b0v, acc[j][1] + b1v);
            *(float2*)&out[(size_t)(r_g + 8) * D_ + c] = make_float2(acc[j][2] + b0v, acc[j][3] + b1v);
        }
    } else {
        // v projection stored transposed: g_vt[b][d][s]
        int b = r_g >> 12, s0 = r_g & (S_ - 1);
        float* out = g_vt + (size_t)b * D_ * S_;
        #pragma unroll
        for (int j = 0; j < 8; j++) {
            int c = 8 * j + 2 * t;
            float b0v = __ldg(&bias[c]), b1v = __ldg(&bias[c + 1]);
            out[(size_t)c * S_ + s0]           = acc[j][0] + b0v;
            out[(size_t)(c + 1) * S_ + s0]     = acc[j][1] + b1v;
            out[(size_t)c * S_ + s0 + 8]       = acc[j][2] + b0v;
            out[(size_t)(c + 1) * S_ + s0 + 8] = acc[j][3] + b1v;
        }
    }
}

// ---------------------------------------------------------------------------
// Kernel 2: causal flash attention, tf32 mma.  grid=(32,8), block=256 (8 warps).
// BQ=128 query rows per block, k-tiles of BK=64.  Warp w: rows 16w..16w+15.
// smem: Qs[128] + Ks[64] + Vts[64] + Ps[128], each [.][SSTR] floats.
// ---------------------------------------------------------------------------
#define ASMEM ((BQ + BK + BK + BQ) * SSTR * (int)sizeof(float))

__global__ void __launch_bounds__(256, 2) attn_kernel(float* __restrict__ out)
{
    extern __shared__ float sm[];
    float* Qs  = sm;                    // [128][SSTR]  [qrow][d]
    float* Ks  = Qs  + BQ * SSTR;       // [64][SSTR]   [key][d]
    float* Vts = Ks  + BK * SSTR;       // [64][SSTR]   [d][key]
    float* Ps  = Vts + BK * SSTR;       // [128][SSTR]  [qrow][key]

    const int b  = blockIdx.y;
    const int qt = gridDim.x - 1 - blockIdx.x;   // heavy tiles first
    const int tid = threadIdx.x;
    const int w = tid >> 5, lane = tid & 31, g = lane >> 2, t = lane & 3;

    const float* q  = g_q  + (size_t)b * S_ * D_;
    const float* kp = g_k  + (size_t)b * S_ * D_;
    const float* vt = g_vt + (size_t)b * D_ * S_;

    #pragma unroll
    for (int i = 0; i < 8; i++) {                 // Q tile 128x64
        int e = tid + i * 256;
        int r = e >> 4, c4 = (e & 15) * 4;
        float4 v = *(const float4*)&q[(size_t)(qt * BQ + r) * D_ + c4];
        float* d = &Qs[r * SSTR + c4];
        d[0] = tf(v.x); d[1] = tf(v.y); d[2] = tf(v.z); d[3] = tf(v.w);
    }

    float o[8][4] = {};
    float m0 = -1e30f, m1 = -1e30f, l0 = 0.f, l1 = 0.f;
    const float scale = 0.125f;                   // 1/sqrt(64)
    const int nkt = 2 * qt + 2;

    for (int kt = 0; kt < nkt; kt++) {
        __syncthreads();                          // prev tile's mma reads done
        #pragma unroll
        for (int i = 0; i < 4; i++) {             // K tile [key][d]
            int e = tid + i * 256;
            int r = e >> 4, c4 = (e & 15) * 4;
            float4 v = *(const float4*)&kp[(size_t)(kt * BK + r) * D_ + c4];
            float* d = &Ks[r * SSTR + c4];
            d[0] = tf(v.x); d[1] = tf(v.y); d[2] = tf(v.z); d[3] = tf(v.w);
        }
        #pragma unroll
        for (int i = 0; i < 4; i++) {             // V^T tile [d][key]
            int e = tid + i * 256;
            int r = e >> 4, c4 = (e & 15) * 4;
            float4 v = *(const float4*)&vt[(size_t)r * S_ + kt * BK + c4];
            float* d = &Vts[r * SSTR + c4];
            d[0] = tf(v.x); d[1] = tf(v.y); d[2] = tf(v.z); d[3] = tf(v.w);
        }
        __syncthreads();

        // S = Q K^T
        float sc[8][4] = {};
        #pragma unroll
        for (int s = 0; s < 8; s++) {
            const float* ap = &Qs[(16 * w + g) * SSTR + 8 * s + t];
            unsigned a0 = __float_as_uint(ap[0]);
            unsigned a1 = __float_as_uint(ap[8 * SSTR]);
            unsigned a2 = __float_as_uint(ap[4]);
            unsigned a3 = __float_as_uint(ap[8 * SSTR + 4]);
            #pragma unroll
            for (int j = 0; j < 8; j++) {
                // B[k][n] = K[key=8j+g][d=8s+t]
                unsigned b0 = __float_as_uint(Ks[(8 * j + g) * SSTR + 8 * s + t]);
                unsigned b1 = __float_as_uint(Ks[(8 * j + g) * SSTR + 8 * s + t + 4]);
                mma8(sc[j], a0, a1, a2, a3, b0, b1);
            }
        }

        #pragma unroll
        for (int j = 0; j < 8; j++) {
            sc[j][0] *= scale; sc[j][1] *= scale; sc[j][2] *= scale; sc[j][3] *= scale;
        }
        if (kt >= nkt - 2) {                      // only diagonal tiles mask
            const int row_g = qt * BQ + 16 * w + g;
            #pragma unroll
            for (int j = 0; j < 8; j++) {
                int key = kt * BK + 8 * j + 2 * t;
                if (key     > row_g)     sc[j][0] = -1e30f;
                if (key + 1 > row_g)     sc[j][1] = -1e30f;
                if (key     > row_g + 8) sc[j][2] = -1e30f;
                if (key + 1 > row_g + 8) sc[j][3] = -1e30f;
            }
        }

        // online softmax; rows g (regs 0,1) and g+8 (regs 2,3) fully in-warp
        float mt0 = -1e30f, mt1 = -1e30f;
        #pragma unroll
        for (int j = 0; j < 8; j++) {
            mt0 = fmaxf(mt0, fmaxf(sc[j][0], sc[j][1]));
            mt1 = fmaxf(mt1, fmaxf(sc[j][2], sc[j][3]));
        }
        mt0 = fmaxf(mt0, __shfl_xor_sync(~0u, mt0, 1));
        mt0 = fmaxf(mt0, __shfl_xor_sync(~0u, mt0, 2));
        mt1 = fmaxf(mt1, __shfl_xor_sync(~0u, mt1, 1));
        mt1 = fmaxf(mt1, __shfl_xor_sync(~0u, mt1, 2));
        float mn0 = fmaxf(m0, mt0), mn1 = fmaxf(m1, mt1);
        float c0 = __expf(m0 - mn0), c1 = __expf(m1 - mn1);
        m0 = mn0; m1 = mn1;

        float rs0 = 0.f, rs1 = 0.f;
        float* prow0 = &Ps[(16 * w + g) * SSTR];
        float* prow1 = prow0 + 8 * SSTR;
        #pragma unroll
        for (int j = 0; j < 8; j++) {
            float e0 = __expf(sc[j][0] - mn0), e1 = __expf(sc[j][1] - mn0);
            float e2 = __expf(sc[j][2] - mn1), e3 = __expf(sc[j][3] - mn1);
            rs0 += e0 + e1; rs1 += e2 + e3;
            int c = 8 * j + 2 * t;
            *(float2*)&prow0[c] = make_float2(tf(e0), tf(e1));
            *(float2*)&prow1[c] = make_float2(tf(e2), tf(e3));
        }
        rs0 += __shfl_xor_sync(~0u, rs0, 1); rs0 += __shfl_xor_sync(~0u, rs0, 2);
        rs1 += __shfl_xor_sync(~0u, rs1, 1); rs1 += __shfl_xor_sync(~0u, rs1, 2);
        l0 = l0 * c0 + rs0; l1 = l1 * c1 + rs1;
        #pragma unroll
        for (int j = 0; j < 8; j++) {
            o[j][0] *= c0; o[j][1] *= c0; o[j][2] *= c1; o[j][3] *= c1;
        }
        __syncwarp();   // P rows of this warp written before frag reads (same warp only)

        // O += P V
        #pragma unroll
        for (int s = 0; s < 8; s++) {
            const float* ap = &Ps[(16 * w + g) * SSTR + 8 * s + t];
            unsigned a0 = __float_as_uint(ap[0]);
            unsigned a1 = __float_as_uint(ap[8 * SSTR]);
            unsigned a2 = __float_as_uint(ap[4]);
            unsigned a3 = __float_as_uint(ap[8 * SSTR + 4]);
            #pragma unroll
            for (int j = 0; j < 8; j++) {
                // B[k][n] = V[key=8s+t][d=8j+g] = Vts[d][key]
                unsigned b0 = __float_as_uint(Vts[(8 * j + g) * SSTR + 8 * s + t]);
                unsigned b1 = __float_as_uint(Vts[(8 * j + g) * SSTR + 8 * s + t + 4]);
                mma8(o[j], a0, a1, a2, a3, b0, b1);
            }
        }
    }

    float i0 = 1.f / l0, i1 = 1.f / l1;
    const int r_g = qt * BQ + 16 * w + g;
    float* op = out + ((size_t)b * S_ + r_g) * D_;
    #pragma unroll
    for (int j = 0; j < 8; j++) {
        int c = 8 * j + 2 * t;
        *(float2*)&op[c]          = make_float2(o[j][0] * i0, o[j][1] * i0);
        *(float2*)&op[8 * D_ + c] = make_float2(o[j][2] * i1, o[j][3] * i1);
    }
}

// ---------------------------------------------------------------------------
extern "C" void kernel_launch(void* const* d_in, const int* in_sizes, int n_in,
                              void* d_out, int out_size)
{
    const float* x  = (const float*)d_in[0];
    const float* Wq = (const float*)d_in[1];
    const float* bq = (const float*)d_in[2];
    const float* Wk = (const float*)d_in[3];
    const float* bk = (const float*)d_in[4];
    const float* Wv = (const float*)d_in[5];
    const float* bv = (const float*)d_in[6];
    float* out = (float*)d_out;

    cudaFuncSetAttribute(qkv_kernel,  cudaFuncAttributeMaxDynamicSharedMemorySize, QKV_SMEM);
    cudaFuncSetAttribute(attn_kernel, cudaFuncAttributeMaxDynamicSharedMemorySize, ASMEM);

    wt_kernel<<<(D_ * H_ + 255) / 256, 256>>>(Wq, Wk, Wv);

    dim3 g1((B_ * S_) / BQ, 3);            // 256 x 3
    qkv_kernel<<<g1, 256, QKV_SMEM>>>(x, bq, bk, bv);

    dim3 g2(S_ / BQ, B_);                  // 32 x 8
    attn_kernel<<<g2, 256, ASMEM>>>(out);
}

// round 5
// speedup vs baseline: 3.6133x; 1.4857x over previous
#include <cuda_runtime.h>
#include <cstdint>

#define B_  8
#define S_  4096
#define H_  768
#define D_  64
#define BQ  128
#define BK  64
#define SSTR 68   // smem row stride; 68 % 32 == 4 -> conflict-free frag loads

// scratch
__device__ float g_q [B_ * S_ * D_];        // [b*S + s][d]
__device__ float g_k [B_ * S_ * D_];        // [b*S + s][d]
__device__ float g_vt[B_ * D_ * S_];        // transposed: [b][d][s]
__device__ float g_wt[3][D_ * H_];          // W^T: [n][k]

// split-K partial buffers: index pi = (b*32+qt)*3 + chunk
__device__ float g_po[8 * 32 * 3 * 128 * 64];   // unnormalized O
__device__ float g_pm[8 * 32 * 3 * 128];        // row max
__device__ float g_pl[8 * 32 * 3 * 128];        // row sum

#define NCHUNK(qt) ((qt) < 12 ? 1 : ((qt) < 24 ? 2 : 3))

__device__ __forceinline__ unsigned f2tf(float f) {
    unsigned u; asm("cvt.rna.tf32.f32 %0, %1;" : "=r"(u) : "f"(f)); return u;
}
__device__ __forceinline__ float tf(float f) { return __uint_as_float(f2tf(f)); }

__device__ __forceinline__ void mma8(float* c, unsigned a0, unsigned a1, unsigned a2, unsigned a3,
                                     unsigned b0, unsigned b1) {
    asm("mma.sync.aligned.m16n8k8.row.col.f32.tf32.tf32.f32 "
        "{%0,%1,%2,%3}, {%4,%5,%6,%7}, {%8,%9}, {%0,%1,%2,%3};"
        : "+f"(c[0]), "+f"(c[1]), "+f"(c[2]), "+f"(c[3])
        : "r"(a0), "r"(a1), "r"(a2), "r"(a3), "r"(b0), "r"(b1));
}

// ---------------------------------------------------------------------------
// Kernel 0: transpose W into g_wt
// ---------------------------------------------------------------------------
__global__ void wt_kernel(const float* __restrict__ Wq,
                          const float* __restrict__ Wk,
                          const float* __restrict__ Wv) {
    int idx = blockIdx.x * blockDim.x + threadIdx.x;
    if (idx >= D_ * H_) return;
    int n = idx / H_, k = idx % H_;
    g_wt[0][idx] = Wq[k * D_ + n];
    g_wt[1][idx] = Wk[k * D_ + n];
    g_wt[2][idx] = Wv[k * D_ + n];
}

// ---------------------------------------------------------------------------
// Kernel 1: QKV projection, tf32 mma.sync (proven R3 version).
// ---------------------------------------------------------------------------
#define QKV_SMEM ((BQ + 64) * SSTR * (int)sizeof(float))

__global__ void __launch_bounds__(256, 2) qkv_kernel(
    const float* __restrict__ x,
    const float* __restrict__ bq, const float* __restrict__ bk, const float* __restrict__ bv)
{
    extern __shared__ float sm[];
    float* xs = sm;                 // [128][SSTR]
    float* ws = sm + BQ * SSTR;     // [64][SSTR]

    const int p = blockIdx.y;
    const float* wt   = g_wt[p];
    const float* bias = (p == 0) ? bq : ((p == 1) ? bk : bv);

    const int tid = threadIdx.x;
    const int w = tid >> 5, lane = tid & 31, g = lane >> 2, t = lane & 3;
    const int row0 = blockIdx.x * BQ;

    float acc[8][4] = {};

    for (int k0 = 0; k0 < H_; k0 += 64) {
        __syncthreads();
        #pragma unroll
        for (int i = 0; i < 8; i++) {
            int e = tid + i * 256;
            int r = e >> 4, c4 = (e & 15) * 4;
            float4 v = *(const float4*)&x[(size_t)(row0 + r) * H_ + k0 + c4];
            float* d = &xs[r * SSTR + c4];
            d[0] = tf(v.x); d[1] = tf(v.y); d[2] = tf(v.z); d[3] = tf(v.w);
        }
        #pragma unroll
        for (int i = 0; i < 4; i++) {
            int e = tid + i * 256;
            int r = e >> 4, c4 = (e & 15) * 4;
            float4 v = *(const float4*)&wt[(size_t)r * H_ + k0 + c4];
            float* d = &ws[r * SSTR + c4];
            d[0] = tf(v.x); d[1] = tf(v.y); d[2] = tf(v.z); d[3] = tf(v.w);
        }
        __syncthreads();

        #pragma unroll
        for (int s = 0; s < 8; s++) {
            const float* ap = &xs[(16 * w + g) * SSTR + 8 * s + t];
            unsigned a0 = __float_as_uint(ap[0]);
            unsigned a1 = __float_as_uint(ap[8 * SSTR]);
            unsigned a2 = __float_as_uint(ap[4]);
            unsigned a3 = __float_as_uint(ap[8 * SSTR + 4]);
            #pragma unroll
            for (int j = 0; j < 8; j++) {
                unsigned b0 = __float_as_uint(ws[(8 * j + g) * SSTR + 8 * s + t]);
                unsigned b1 = __float_as_uint(ws[(8 * j + g) * SSTR + 8 * s + t + 4]);
                mma8(acc[j], a0, a1, a2, a3, b0, b1);
            }
        }
    }

    const int r_g = row0 + 16 * w + g;
    if (p < 2) {
        float* out = (p == 0) ? g_q : g_k;
        #pragma unroll
        for (int j = 0; j < 8; j++) {
            int c = 8 * j + 2 * t;
            float b0v = __ldg(&bias[c]), b1v = __ldg(&bias[c + 1]);
            *(float2*)&out[(size_t)r_g * D_ + c]       = make_float2(acc[j][0] + b0v, acc[j][1] + b1v);
            *(float2*)&out[(size_t)(r_g + 8) * D_ + c] = make_float2(acc[j][2] + b0v, acc[j][3] + b1v);
        }
    } else {
        int b = r_g >> 12, s0 = r_g & (S_ - 1);
        float* out = g_vt + (size_t)b * D_ * S_;
        #pragma unroll
        for (int j = 0; j < 8; j++) {
            int c = 8 * j + 2 * t;
            float b0v = __ldg(&bias[c]), b1v = __ldg(&bias[c + 1]);
            out[(size_t)c * S_ + s0]           = acc[j][0] + b0v;
            out[(size_t)(c + 1) * S_ + s0]     = acc[j][1] + b1v;
            out[(size_t)c * S_ + s0 + 8]       = acc[j][2] + b0v;
            out[(size_t)(c + 1) * S_ + s0 + 8] = acc[j][3] + b1v;
        }
    }
}

// ---------------------------------------------------------------------------
// Kernel 2: split-K causal flash attention chunk.
// 480 CTAs = 60 work items x 8 batches, launched heaviest-first (LPT).
// Work item w_: [0,24): qt=23-(w_/2) 2-way split; [24,48): qt=24+(u/3) 3-way;
// [48,60): qt=59-w_ single chunk (writes out directly).
// ---------------------------------------------------------------------------
#define ASMEM ((BQ + BK + BK + BQ) * SSTR * (int)sizeof(float))

__global__ void __launch_bounds__(256, 2) attn_chunk_kernel(float* __restrict__ out)
{
    extern __shared__ float sm[];
    float* Qs  = sm;
    float* Ks  = Qs  + BQ * SSTR;
    float* Vts = Ks  + BK * SSTR;
    float* Ps  = Vts + BK * SSTR;

    // decode work item
    const int b  = blockIdx.x & 7;
    const int w_ = blockIdx.x >> 3;        // 0..59
    int qt, chunk;
    if (w_ < 24)      { qt = 23 - (w_ >> 1);        chunk = w_ & 1; }
    else if (w_ < 48) { int u = w_ - 24; qt = 24 + u / 3; chunk = u % 3; }
    else              { qt = 59 - w_;               chunk = 0; }
    const int nkt = 2 * qt + 2;
    const int nc  = NCHUNK(qt);
    const int base = nkt / nc, rem = nkt % nc;
    const int k0  = chunk * base + (chunk < rem ? chunk : rem);
    const int k1  = k0 + base + (chunk < rem ? 1 : 0);

    const int tid = threadIdx.x;
    const int w = tid >> 5, lane = tid & 31, g = lane >> 2, t = lane & 3;

    const float* q  = g_q  + (size_t)b * S_ * D_;
    const float* kp = g_k  + (size_t)b * S_ * D_;
    const float* vt = g_vt + (size_t)b * D_ * S_;

    #pragma unroll
    for (int i = 0; i < 8; i++) {                 // Q tile
        int e = tid + i * 256;
        int r = e >> 4, c4 = (e & 15) * 4;
        float4 v = *(const float4*)&q[(size_t)(qt * BQ + r) * D_ + c4];
        float* d = &Qs[r * SSTR + c4];
        d[0] = tf(v.x); d[1] = tf(v.y); d[2] = tf(v.z); d[3] = tf(v.w);
    }

    float o[8][4] = {};
    float m0 = -1e30f, m1 = -1e30f, l0 = 0.f, l1 = 0.f;
    const float scale = 0.125f;

    for (int kt = k0; kt < k1; kt++) {
        __syncthreads();
        #pragma unroll
        for (int i = 0; i < 4; i++) {
            int e = tid + i * 256;
            int r = e >> 4, c4 = (e & 15) * 4;
            float4 v = *(const float4*)&kp[(size_t)(kt * BK + r) * D_ + c4];
            float* d = &Ks[r * SSTR + c4];
            d[0] = tf(v.x); d[1] = tf(v.y); d[2] = tf(v.z); d[3] = tf(v.w);
        }
        #pragma unroll
        for (int i = 0; i < 4; i++) {
            int e = tid + i * 256;
            int r = e >> 4, c4 = (e & 15) * 4;
            float4 v = *(const float4*)&vt[(size_t)r * S_ + kt * BK + c4];
            float* d = &Vts[r * SSTR + c4];
            d[0] = tf(v.x); d[1] = tf(v.y); d[2] = tf(v.z); d[3] = tf(v.w);
        }
        __syncthreads();

        float sc[8][4] = {};
        #pragma unroll
        for (int s = 0; s < 8; s++) {
            const float* ap = &Qs[(16 * w + g) * SSTR + 8 * s + t];
            unsigned a0 = __float_as_uint(ap[0]);
            unsigned a1 = __float_as_uint(ap[8 * SSTR]);
            unsigned a2 = __float_as_uint(ap[4]);
            unsigned a3 = __float_as_uint(ap[8 * SSTR + 4]);
            #pragma unroll
            for (int j = 0; j < 8; j++) {
                unsigned b0 = __float_as_uint(Ks[(8 * j + g) * SSTR + 8 * s + t]);
                unsigned b1 = __float_as_uint(Ks[(8 * j + g) * SSTR + 8 * s + t + 4]);
                mma8(sc[j], a0, a1, a2, a3, b0, b1);
            }
        }

        #pragma unroll
        for (int j = 0; j < 8; j++) {
            sc[j][0] *= scale; sc[j][1] *= scale; sc[j][2] *= scale; sc[j][3] *= scale;
        }
        if (kt >= nkt - 2) {                      // diagonal masking (global kt)
            const int row_g = qt * BQ + 16 * w + g;
            #pragma unroll
            for (int j = 0; j < 8; j++) {
                int key = kt * BK + 8 * j + 2 * t;
                if (key     > row_g)     sc[j][0] = -1e30f;
                if (key + 1 > row_g)     sc[j][1] = -1e30f;
                if (key     > row_g + 8) sc[j][2] = -1e30f;
                if (key + 1 > row_g + 8) sc[j][3] = -1e30f;
            }
        }

        float mt0 = -1e30f, mt1 = -1e30f;
        #pragma unroll
        for (int j = 0; j < 8; j++) {
            mt0 = fmaxf(mt0, fmaxf(sc[j][0], sc[j][1]));
            mt1 = fmaxf(mt1, fmaxf(sc[j][2], sc[j][3]));
        }
        mt0 = fmaxf(mt0, __shfl_xor_sync(~0u, mt0, 1));
        mt0 = fmaxf(mt0, __shfl_xor_sync(~0u, mt0, 2));
        mt1 = fmaxf(mt1, __shfl_xor_sync(~0u, mt1, 1));
        mt1 = fmaxf(mt1, __shfl_xor_sync(~0u, mt1, 2));
        float mn0 = fmaxf(m0, mt0), mn1 = fmaxf(m1, mt1);
        float c0 = __expf(m0 - mn0), c1 = __expf(m1 - mn1);
        m0 = mn0; m1 = mn1;

        float rs0 = 0.f, rs1 = 0.f;
        float* prow0 = &Ps[(16 * w + g) * SSTR];
        float* prow1 = prow0 + 8 * SSTR;
        #pragma unroll
        for (int j = 0; j < 8; j++) {
            float e0 = __expf(sc[j][0] - mn0), e1 = __expf(sc[j][1] - mn0);
            float e2 = __expf(sc[j][2] - mn1), e3 = __expf(sc[j][3] - mn1);
            rs0 += e0 + e1; rs1 += e2 + e3;
            int c = 8 * j + 2 * t;
            *(float2*)&prow0[c] = make_float2(tf(e0), tf(e1));
            *(float2*)&prow1[c] = make_float2(tf(e2), tf(e3));
        }
        rs0 += __shfl_xor_sync(~0u, rs0, 1); rs0 += __shfl_xor_sync(~0u, rs0, 2);
        rs1 += __shfl_xor_sync(~0u, rs1, 1); rs1 += __shfl_xor_sync(~0u, rs1, 2);
        l0 = l0 * c0 + rs0; l1 = l1 * c1 + rs1;
        #pragma unroll
        for (int j = 0; j < 8; j++) {
            o[j][0] *= c0; o[j][1] *= c0; o[j][2] *= c1; o[j][3] *= c1;
        }
        __syncwarp();

        #pragma unroll
        for (int s = 0; s < 8; s++) {
            const float* ap = &Ps[(16 * w + g) * SSTR + 8 * s + t];
            unsigned a0 = __float_as_uint(ap[0]);
            unsigned a1 = __float_as_uint(ap[8 * SSTR]);
            unsigned a2 = __float_as_uint(ap[4]);
            unsigned a3 = __float_as_uint(ap[8 * SSTR + 4]);
            #pragma unroll
            for (int j = 0; j < 8; j++) {
                unsigned b0 = __float_as_uint(Vts[(8 * j + g) * SSTR + 8 * s + t]);
                unsigned b1 = __float_as_uint(Vts[(8 * j + g) * SSTR + 8 * s + t + 4]);
                mma8(o[j], a0, a1, a2, a3, b0, b1);
            }
        }
    }

    const int rl0 = 16 * w + g;                   // local rows rl0, rl0+8
    if (nc == 1) {
        float i0 = 1.f / l0, i1 = 1.f / l1;
        float* op = out + ((size_t)b * S_ + qt * BQ + rl0) * D_;
        #pragma unroll
        for (int j = 0; j < 8; j++) {
            int c = 8 * j + 2 * t;
            *(float2*)&op[c]          = make_float2(o[j][0] * i0, o[j][1] * i0);
            *(float2*)&op[8 * D_ + c] = make_float2(o[j][2] * i1, o[j][3] * i1);
        }
    } else {
        const int pi = (b * 32 + qt) * 3 + chunk;
        float* po = g_po + (size_t)pi * 128 * 64;
        #pragma unroll
        for (int j = 0; j < 8; j++) {
            int c = 8 * j + 2 * t;
            *(float2*)&po[rl0 * 64 + c]       = make_float2(o[j][0], o[j][1]);
            *(float2*)&po[(rl0 + 8) * 64 + c] = make_float2(o[j][2], o[j][3]);
        }
        if (t == 0) {
            g_pm[pi * 128 + rl0]     = m0;
            g_pm[pi * 128 + rl0 + 8] = m1;
            g_pl[pi * 128 + rl0]     = l0;
            g_pl[pi * 128 + rl0 + 8] = l1;
        }
    }
}

// ---------------------------------------------------------------------------
// Kernel 3: merge split-K partials for qt >= 12.  grid=(20,8), block=256.
// ---------------------------------------------------------------------------
__global__ void __launch_bounds__(256) merge_kernel(float* __restrict__ out)
{
    const int qt = 12 + blockIdx.x;
    const int b  = blockIdx.y;
    const int nc = NCHUNK(qt);
    const int pib = (b * 32 + qt) * 3;

    for (int e = threadIdx.x; e < 128 * 64; e += 256) {
        const int r = e >> 6, col = e & 63;
        float M = -1e30f;
        #pragma unroll
        for (int c = 0; c < 3; c++)
            if (c < nc) M = fmaxf(M, g_pm[(pib + c) * 128 + r]);
        float L = 0.f, O = 0.f;
        #pragma unroll
        for (int c = 0; c < 3; c++)
            if (c < nc) {
                float wgt = __expf(g_pm[(pib + c) * 128 + r] - M);
                L += g_pl[(pib + c) * 128 + r] * wgt;
                O += g_po[(size_t)(pib + c) * 8192 + e] * wgt;
            }
        out[((size_t)b * S_ + qt * BQ + r) * D_ + col] = O / L;
    }
}

// ---------------------------------------------------------------------------
extern "C" void kernel_launch(void* const* d_in, const int* in_sizes, int n_in,
                              void* d_out, int out_size)
{
    const float* x  = (const float*)d_in[0];
    const float* Wq = (const float*)d_in[1];
    const float* bq = (const float*)d_in[2];
    const float* Wk = (const float*)d_in[3];
    const float* bk = (const float*)d_in[4];
    const float* Wv = (const float*)d_in[5];
    const float* bv = (const float*)d_in[6];
    float* out = (float*)d_out;

    cudaFuncSetAttribute(qkv_kernel,        cudaFuncAttributeMaxDynamicSharedMemorySize, QKV_SMEM);
    cudaFuncSetAttribute(attn_chunk_kernel, cudaFuncAttributeMaxDynamicSharedMemorySize, ASMEM);

    wt_kernel<<<(D_ * H_ + 255) / 256, 256>>>(Wq, Wk, Wv);

    dim3 g1((B_ * S_) / BQ, 3);
    qkv_kernel<<<g1, 256, QKV_SMEM>>>(x, bq, bk, bv);

    attn_chunk_kernel<<<480, 256, ASMEM>>>(out);

    dim3 g3(20, 8);
    merge_kernel<<<g3, 256>>>(out);
}